// round 17
// baseline (speedup 1.0000x reference)
#include <cuda_runtime.h>
#include <cuda_fp16.h>
#include <cuda_bf16.h>
#include <cstdint>
#include <cstddef>

#define TLEN   2048
#define NBATCH 2
#define DMODEL 1024
#define DSTATE 64
#define DCONV  4
#define DINNER 2048
#define DPROJ  4288
#define DTRANK 64
#define MROWS  (NBATCH * TLEN)   // 4096

// ---------------- scratch (static device globals; no allocation) ----------------
__device__ float g_proj [(size_t)MROWS * DPROJ];   // 70.3 MB
__device__ float g_delta[(size_t)MROWS * DINNER];  // 33.6 MB

// fp16 operand buffers (16B aligned for cp.async / vector loads)
__device__ __align__(16) __half g_xh  [(size_t)MROWS * DMODEL];
__device__ __align__(16) __half g_w1h [(size_t)DPROJ * DMODEL];
__device__ __align__(16) __half g_w2h [(size_t)DMODEL * DINNER];
__device__ __align__(16) __half g_yh  [(size_t)MROWS * DINNER];
// hi/lo split operands for the dt GEMM (exact to 2^-22)
__device__ __align__(16) __half g_drh [(size_t)MROWS * DTRANK];
__device__ __align__(16) __half g_drl [(size_t)MROWS * DTRANK];
__device__ __align__(16) __half g_dtwh[(size_t)DINNER * DTRANK];
__device__ __align__(16) __half g_dtwl[(size_t)DINNER * DTRANK];

// ---------------- small math helpers ----------------
__device__ __forceinline__ float ex2f(float x) {
    float y;
    asm("ex2.approx.f32 %0, %1;" : "=f"(y) : "f"(x));
    return y;
}
__device__ __forceinline__ float sigmoidf_(float x) {
    return 1.0f / (1.0f + __expf(-x));
}
__device__ __forceinline__ float softplusf_(float x) {
    return (x > 20.0f) ? x : log1pf(__expf(x));
}

// ---------------- sm_80-level async/MMA primitives (legal under compute_103) ----------------
__device__ __forceinline__ uint32_t smem_to_u32(const void* p) {
    uint32_t a;
    asm("{ .reg .u64 t; cvta.to.shared.u64 t, %1; cvt.u32.u64 %0, t; }" : "=r"(a) : "l"(p));
    return a;
}
__device__ __forceinline__ void ldsm4(uint32_t* r, uint32_t addr) {
    asm volatile("ldmatrix.sync.aligned.m8n8.x4.shared.b16 {%0,%1,%2,%3}, [%4];"
                 : "=r"(r[0]), "=r"(r[1]), "=r"(r[2]), "=r"(r[3]) : "r"(addr));
}
__device__ __forceinline__ void mma16816h(float* d, const uint32_t* a, const uint32_t* b) {
    asm volatile(
        "mma.sync.aligned.m16n8k16.row.col.f32.f16.f16.f32 "
        "{%0,%1,%2,%3}, {%4,%5,%6,%7}, {%8,%9}, {%0,%1,%2,%3};"
        : "+f"(d[0]), "+f"(d[1]), "+f"(d[2]), "+f"(d[3])
        : "r"(a[0]), "r"(a[1]), "r"(a[2]), "r"(a[3]), "r"(b[0]), "r"(b[1]));
}
__device__ __forceinline__ void cpa16(uint32_t saddr, const void* g) {
    asm volatile("cp.async.cg.shared.global [%0], [%1], 16;" :: "r"(saddr), "l"(g));
}
__device__ __forceinline__ void cpa_commit() {
    asm volatile("cp.async.commit_group;" ::: "memory");
}
template<int N_>
__device__ __forceinline__ void cpa_wait() {
    asm volatile("cp.async.wait_group %0;" :: "n"(N_) : "memory");
}

// ---------------- fp32 -> fp16 convert ----------------
__global__ __launch_bounds__(256)
void cvt_fp16_kernel(const float* __restrict__ src, __half* __restrict__ dst, int n4)
{
    int i = blockIdx.x * blockDim.x + threadIdx.x;
    if (i >= n4) return;
    float4 v = ((const float4*)src)[i];
    __half h[4];
    h[0] = __float2half(v.x); h[1] = __float2half(v.y);
    h[2] = __float2half(v.z); h[3] = __float2half(v.w);
    *(uint2*)(dst + 4 * (size_t)i) = *(uint2*)h;
}

// ---------------- fp32 -> fp16 hi/lo split (strided source) ----------------
__global__ __launch_bounds__(256)
void split_f16pair_kernel(const float* __restrict__ src, int lda, int cols,
                          __half* __restrict__ hi, __half* __restrict__ lo, int n4)
{
    int i = blockIdx.x * blockDim.x + threadIdx.x;
    if (i >= n4) return;
    int perRow = cols >> 2;
    int row = i / perRow;
    int c = (i - row * perRow) * 4;
    float4 v = *(const float4*)(src + (size_t)row * lda + c);
    float vv[4] = {v.x, v.y, v.z, v.w};
    __half h[4], l[4];
#pragma unroll
    for (int j = 0; j < 4; j++) {
        h[j] = __float2half(vv[j]);
        l[j] = __float2half(vv[j] - __half2float(h[j]));
    }
    size_t o = (size_t)row * cols + c;
    *(uint2*)(hi + o) = *(uint2*)h;
    *(uint2*)(lo + o) = *(uint2*)l;
}

// ---------------- HMMA fp16 GEMM: C[M,N] = A[M,K] @ B[N,K]^T ----------------
// CTA 128x128, 8 warps (warp tile m32 x n64), BK=64, 3-stage cp.async pipeline.
#define ROWB   144
#define TILEB  (128 * ROWB)      // 18432
#define STAGEB (2 * TILEB)       // 36864
#define NSTG   3
#define SMEMB  (NSTG * STAGEB)   // 110592

__global__ void __launch_bounds__(256, 2)
gemm_mma_fp16(const __half* __restrict__ A, const __half* __restrict__ B,
              float* __restrict__ C, int M, int N, int K)
{
    extern __shared__ __align__(128) char smem[];
    const uint32_t sb = smem_to_u32(smem);

    const int tid  = threadIdx.x;
    const int wid  = tid >> 5;
    const int lane = tid & 31;
    const int m0 = blockIdx.y * 128;
    const int n0 = blockIdx.x * 128;
    const int wm = (wid & 3) * 32;
    const int wn = (wid >> 2) * 64;

    const int NC = K >> 6;

    float acc[2][8][4];
#pragma unroll
    for (int a = 0; a < 2; a++)
#pragma unroll
        for (int b = 0; b < 8; b++)
#pragma unroll
            for (int c = 0; c < 4; c++) acc[a][b][c] = 0.0f;

    auto bufof = [](int cidx) { return cidx - (cidx / NSTG) * NSTG; };

    auto load_stage = [&](int cidx) {
        const int k0 = cidx << 6;
        uint32_t base = sb + bufof(cidx) * STAGEB;
#pragma unroll
        for (int it = 0; it < 8; it++) {
            int idx = it * 256 + tid;
            int row = (idx >> 3) & 127;
            int c16 = idx & 7;
            uint32_t soff = (uint32_t)(row * ROWB + c16 * 16);
            if (idx < 1024) {
                size_t gA = (size_t)(m0 + row) * K + k0 + c16 * 8;
                cpa16(base + soff, A + gA);
            } else {
                int gn = n0 + row;
                if (gn >= N) gn = N - 1;
                size_t gB = (size_t)gn * K + k0 + c16 * 8;
                cpa16(base + TILEB + soff, B + gB);
            }
        }
    };

    load_stage(0); cpa_commit();
    if (NC > 1) load_stage(1);
    cpa_commit();

    for (int cidx = 0; cidx < NC; cidx++) {
        cpa_wait<1>();
        __syncthreads();

        if (cidx + 2 < NC) load_stage(cidx + 2);
        cpa_commit();

        const uint32_t base = sb + bufof(cidx) * STAGEB;
        const uint32_t aB = base;
        const uint32_t bB = base + TILEB;

#pragma unroll
        for (int ks = 0; ks < 4; ks++) {
            uint32_t ah[2][4];
            {
                int rr = ((lane >> 3) & 1) * 8 + (lane & 7);
                int cc = ks * 16 + (lane >> 4) * 8;
#pragma unroll
                for (int mf = 0; mf < 2; mf++) {
                    uint32_t off = (uint32_t)((wm + mf * 16 + rr) * ROWB + cc * 2);
                    ldsm4(ah[mf], aB + off);
                }
            }
            {
                int rr = ((lane >> 4) & 1) * 8 + (lane & 7);
                int cc = ks * 16 + ((lane >> 3) & 1) * 8;
#pragma unroll
                for (int ng = 0; ng < 4; ng++) {
                    uint32_t bh[4];
                    uint32_t off = (uint32_t)((wn + ng * 16 + rr) * ROWB + cc * 2);
                    ldsm4(bh, bB + off);
#pragma unroll
                    for (int mf = 0; mf < 2; mf++) {
                        mma16816h(acc[mf][ng * 2 + 0], ah[mf], &bh[0]);
                        mma16816h(acc[mf][ng * 2 + 1], ah[mf], &bh[2]);
                    }
                }
            }
        }
    }

#pragma unroll
    for (int mf = 0; mf < 2; mf++)
#pragma unroll
        for (int nf = 0; nf < 8; nf++) {
            int rr = m0 + wm + mf * 16 + (lane >> 2);
            int cc = n0 + wn + nf * 8 + (lane & 3) * 2;
            if (cc < N) {
                *(float2*)(C + (size_t)rr * N + cc) =
                    make_float2(acc[mf][nf][0], acc[mf][nf][1]);
                *(float2*)(C + (size_t)(rr + 8) * N + cc) =
                    make_float2(acc[mf][nf][2], acc[mf][nf][3]);
            }
        }
}

// ---------------- dt GEMM: delta = softplus(A @ B^T + bias), hi/lo fp16 split ----------------
// M=4096, N=2048, K=64 fixed. Single K chunk; 3 products (hh + hl + lh) -> fp32-accurate.
#define DT_TILEB (128 * ROWB)            // 18432
#define DT_SMEMB (4 * DT_TILEB)          // 73728 (Ahi, Alo, Bhi, Blo)

__global__ void __launch_bounds__(256, 2)
gemm_dt_split(const __half* __restrict__ Ah, const __half* __restrict__ Al,
              const __half* __restrict__ Bh, const __half* __restrict__ Bl,
              float* __restrict__ C, const float* __restrict__ bias)
{
    extern __shared__ __align__(128) char smem[];
    const uint32_t sb = smem_to_u32(smem);

    const int tid  = threadIdx.x;
    const int wid  = tid >> 5;
    const int lane = tid & 31;
    const int m0 = blockIdx.y * 128;
    const int n0 = blockIdx.x * 128;
    const int wm = (wid & 3) * 32;
    const int wn = (wid >> 2) * 64;

    float acc[2][8][4];
#pragma unroll
    for (int a = 0; a < 2; a++)
#pragma unroll
        for (int b = 0; b < 8; b++)
#pragma unroll
            for (int c = 0; c < 4; c++) acc[a][b][c] = 0.0f;

    // load 4 tiles of [128 rows x 64 fp16 = 128B], 16 chunks/thread
#pragma unroll
    for (int it = 0; it < 16; it++) {
        int idx = it * 256 + tid;            // 0..4095
        int tile = idx >> 10;                // 0:Ah 1:Al 2:Bh 3:Bl
        int rc = idx & 1023;
        int row = rc >> 3;
        int c16 = rc & 7;
        uint32_t soff = (uint32_t)(tile * DT_TILEB + row * ROWB + c16 * 16);
        size_t g = (size_t)((tile < 2 ? m0 : n0) + row) * DTRANK + c16 * 8;
        const __half* src = (tile == 0) ? Ah : (tile == 1) ? Al : (tile == 2) ? Bh : Bl;
        cpa16(sb + soff, src + g);
    }
    cpa_commit();
    cpa_wait<0>();
    __syncthreads();

    const uint32_t aHb = sb;
    const uint32_t aLb = sb + DT_TILEB;
    const uint32_t bHb = sb + 2 * DT_TILEB;
    const uint32_t bLb = sb + 3 * DT_TILEB;

#pragma unroll
    for (int ks = 0; ks < 4; ks++) {
        uint32_t ahh[2][4], all_[2][4];
        {
            int rr = ((lane >> 3) & 1) * 8 + (lane & 7);
            int cc = ks * 16 + (lane >> 4) * 8;
#pragma unroll
            for (int mf = 0; mf < 2; mf++) {
                uint32_t off = (uint32_t)((wm + mf * 16 + rr) * ROWB + cc * 2);
                ldsm4(ahh[mf], aHb + off);
                ldsm4(all_[mf], aLb + off);
            }
        }
        {
            int rr = ((lane >> 4) & 1) * 8 + (lane & 7);
            int cc = ks * 16 + ((lane >> 3) & 1) * 8;
#pragma unroll
            for (int ng = 0; ng < 4; ng++) {
                uint32_t bh[4], bl[4];
                uint32_t off = (uint32_t)((wn + ng * 16 + rr) * ROWB + cc * 2);
                ldsm4(bh, bHb + off);
                ldsm4(bl, bLb + off);
#pragma unroll
                for (int mf = 0; mf < 2; mf++) {
                    mma16816h(acc[mf][ng * 2 + 0], ahh[mf], &bh[0]);
                    mma16816h(acc[mf][ng * 2 + 1], ahh[mf], &bh[2]);
                    mma16816h(acc[mf][ng * 2 + 0], ahh[mf], &bl[0]);
                    mma16816h(acc[mf][ng * 2 + 1], ahh[mf], &bl[2]);
                    mma16816h(acc[mf][ng * 2 + 0], all_[mf], &bh[0]);
                    mma16816h(acc[mf][ng * 2 + 1], all_[mf], &bh[2]);
                }
            }
        }
    }

    // epilogue: softplus(acc + bias[n]) -> fp32 delta
#pragma unroll
    for (int mf = 0; mf < 2; mf++)
#pragma unroll
        for (int nf = 0; nf < 8; nf++) {
            int rr = m0 + wm + mf * 16 + (lane >> 2);
            int cc = n0 + wn + nf * 8 + (lane & 3) * 2;
            float b0 = bias[cc], b1 = bias[cc + 1];
            *(float2*)(C + (size_t)rr * DINNER + cc) =
                make_float2(softplusf_(acc[mf][nf][0] + b0), softplusf_(acc[mf][nf][1] + b1));
            *(float2*)(C + (size_t)(rr + 8) * DINNER + cc) =
                make_float2(softplusf_(acc[mf][nf][2] + b0), softplusf_(acc[mf][nf][3] + b1));
        }
}

// ---------------- selective scan v4b: fused conv+silu, packed (delta, delta*xc) ----------------
#define SW   32    // timesteps per chunk
#define SCH  16    // channels per block
#define SNCH (TLEN / SW)   // 64 chunks

struct ScanSmem {
    float  BC[2][SW][128];      // B (64) then C (64) per timestep     32 KB
    float  D [2][SW][SCH];      // delta (cp.async landing)             4 KB
    float  Z [2][SW][SCH];      // z                                    4 KB
    float  XI[2][SW + 4][SCH];  // x_inner rows t0-3 .. t0+32          4.5 KB
    float  XC[2][SW][SCH];      // conv+silu output                     4 KB
    float2 DU2[2][SW][SCH];     // packed (delta, delta*xc)             8 KB
    float  P [SW][SCH][16];     // per-lane partial h.C                32 KB
    float  Dsm[SCH];
    float  CW[SCH][4];
    float  CB[SCH];
};                               // ~89 KB

__global__ void __launch_bounds__(256, 2)
scan_kernel4(const float* __restrict__ proj,
             const float* __restrict__ delta,
             const float* __restrict__ A_log,
             const float* __restrict__ D_param,
             const float* __restrict__ conv_w,
             const float* __restrict__ conv_b,
             __half* __restrict__ yh,
             float* __restrict__ hT)
{
    extern __shared__ __align__(16) char smraw[];
    ScanSmem* sm = (ScanSmem*)smraw;

    const int tid  = threadIdx.x;
    const int warp = tid >> 5;
    const int lane = tid & 31;
    const int b    = blockIdx.x >> 7;
    const int i0   = (blockIdx.x & 127) * SCH;
    const int chw  = (warp << 1) + (lane >> 4);
    const int i    = i0 + chw;
    const int sub  = lane & 15;
    const int s0   = sub << 2;

    float A2[4];
#pragma unroll
    for (int j = 0; j < 4; j++)
        A2[j] = -__expf(A_log[s0 + j]) * 1.4426950408889634f;

    if (tid < 16) {
        sm->Dsm[tid] = D_param[i0 + tid];
        sm->CB[tid]  = conv_b[i0 + tid];
    } else if (tid < 80) {
        int t2 = tid - 16;
        sm->CW[t2 >> 2][t2 & 3] = conv_w[(i0 + (t2 >> 2)) * DCONV + (t2 & 3)];
    }

    float h0 = 0.f, h1 = 0.f, h2 = 0.f, h3 = 0.f;

    auto fill = [&](int buf, int c) {
        const int t0 = c * SW;
        const float* basebc = proj + ((size_t)(b * TLEN + t0)) * DPROJ + 2 * DINNER;
#pragma unroll
        for (int it = 0; it < 4; it++) {
            int idx = it * 256 + tid;
            int r = idx >> 5, cc = idx & 31;
            cpa16(smem_to_u32(&sm->BC[buf][r][cc * 4]), basebc + (size_t)r * DPROJ + cc * 4);
        }
        if (tid < 128) {
            int r = tid >> 2, cc = (tid & 3) * 4;
            size_t rowi = (size_t)(b * TLEN + t0 + r);
            cpa16(smem_to_u32(&sm->D[buf][r][cc]), delta + rowi * DINNER + i0 + cc);
        } else {
            int t2 = tid - 128;
            int r = t2 >> 2, cc = (t2 & 3) * 4;
            size_t rowi = (size_t)(b * TLEN + t0 + r);
            cpa16(smem_to_u32(&sm->Z[buf][r][cc]), proj + rowi * DPROJ + DINNER + i0 + cc);
        }
        if (tid < 144) {
            int rr = tid >> 2, cc = (tid & 3) * 4;
            int gt = t0 - 3 + rr;
            if (gt >= 0 && gt < TLEN) {
                cpa16(smem_to_u32(&sm->XI[buf][rr][cc]),
                      proj + ((size_t)(b * TLEN + gt)) * DPROJ + i0 + cc);
            } else {
                *(float4*)&sm->XI[buf][rr][cc] = make_float4(0.f, 0.f, 0.f, 0.f);
            }
        }
    };

    fill(0, 0); cpa_commit();
    fill(1, 1); cpa_commit();

    for (int c = 0; c < SNCH; c++) {
        const int buf = c & 1;
        cpa_wait<1>();
        __syncthreads();

        {
            int idx = tid * 2;
            int t = idx >> 4, ch = idx & 15;
#pragma unroll
            for (int v = 0; v < 2; v++) {
                float a = sm->CB[ch + v];
#pragma unroll
                for (int k = 0; k < DCONV; k++)
                    a = fmaf(sm->XI[buf][t + k][ch + v], sm->CW[ch + v][k], a);
                float xcv = a * sigmoidf_(a);
                sm->XC[buf][t][ch + v] = xcv;
                float dv = sm->D[buf][t][ch + v];
                sm->DU2[buf][t][ch + v] = make_float2(dv, dv * xcv);
            }
        }
        __syncthreads();

#pragma unroll 8
        for (int t = 0; t < SW; t++) {
            float2 dd = sm->DU2[buf][t][chw];
            float4 Bv = *(const float4*)&sm->BC[buf][t][s0];
            float4 Cv = *(const float4*)&sm->BC[buf][t][64 + s0];

            h0 = fmaf(ex2f(A2[0] * dd.x), h0, dd.y * Bv.x);
            h1 = fmaf(ex2f(A2[1] * dd.x), h1, dd.y * Bv.y);
            h2 = fmaf(ex2f(A2[2] * dd.x), h2, dd.y * Bv.z);
            h3 = fmaf(ex2f(A2[3] * dd.x), h3, dd.y * Bv.w);

            sm->P[t][chw][sub] =
                fmaf(h0, Cv.x, fmaf(h1, Cv.y, fmaf(h2, Cv.z, h3 * Cv.w)));
        }
        __syncthreads();

        {
            const int t0 = c * SW;
            int t = tid >> 3, chp = (tid & 7) * 2;
            float s0v = 0.f, s1v = 0.f;
            const float4* p0 = (const float4*)&sm->P[t][chp][0];
            const float4* p1 = (const float4*)&sm->P[t][chp + 1][0];
#pragma unroll
            for (int j = 0; j < 4; j++) {
                float4 v0 = p0[j], v1 = p1[j];
                s0v += (v0.x + v0.y) + (v0.z + v0.w);
                s1v += (v1.x + v1.y) + (v1.z + v1.w);
            }
            s0v = fmaf(sm->Dsm[chp],     sm->XC[buf][t][chp],     s0v);
            s1v = fmaf(sm->Dsm[chp + 1], sm->XC[buf][t][chp + 1], s1v);
            float z0 = sm->Z[buf][t][chp], z1 = sm->Z[buf][t][chp + 1];
            s0v *= z0 * sigmoidf_(z0);
            s1v *= z1 * sigmoidf_(z1);
            *(__half2*)(yh + ((size_t)(b * TLEN + t0 + t)) * DINNER + i0 + chp) =
                __floats2half2_rn(s0v, s1v);
        }
        __syncthreads();

        if (c + 2 < SNCH) fill(buf, c + 2);
        cpa_commit();
    }

    *(float4*)(hT + ((size_t)(b * DINNER + i)) * DSTATE + s0) = make_float4(h0, h1, h2, h3);
}

// ---------------- launch ----------------
extern "C" void kernel_launch(void* const* d_in, const int* in_sizes, int n_in,
                              void* d_out, int out_size)
{
    const float* x       = (const float*)d_in[0];   // [2,2048,1024]
    const float* in_proj = (const float*)d_in[1];   // [4288,1024]
    const float* conv_w  = (const float*)d_in[2];   // [2048,1,4]
    const float* conv_b  = (const float*)d_in[3];   // [2048]
    const float* A_log   = (const float*)d_in[4];   // [64]
    const float* D_param = (const float*)d_in[5];   // [2048]
    const float* dt_w    = (const float*)d_in[6];   // [2048,64]
    const float* dt_b    = (const float*)d_in[7];   // [2048]
    const float* out_w   = (const float*)d_in[8];   // [1024,2048]
    float* out = (float*)d_out;                     // out (4194304) then hT (262144)

    float *pproj, *pdelta;
    cudaGetSymbolAddress((void**)&pproj,  g_proj);
    cudaGetSymbolAddress((void**)&pdelta, g_delta);

    __half *xh, *w1h, *w2h, *yh, *drh, *drl, *dtwh, *dtwl;
    cudaGetSymbolAddress((void**)&xh,   g_xh);
    cudaGetSymbolAddress((void**)&w1h,  g_w1h);
    cudaGetSymbolAddress((void**)&w2h,  g_w2h);
    cudaGetSymbolAddress((void**)&yh,   g_yh);
    cudaGetSymbolAddress((void**)&drh,  g_drh);
    cudaGetSymbolAddress((void**)&drl,  g_drl);
    cudaGetSymbolAddress((void**)&dtwh, g_dtwh);
    cudaGetSymbolAddress((void**)&dtwl, g_dtwl);

    cudaFuncSetAttribute(gemm_mma_fp16,
                         cudaFuncAttributeMaxDynamicSharedMemorySize, SMEMB);
    cudaFuncSetAttribute(gemm_dt_split,
                         cudaFuncAttributeMaxDynamicSharedMemorySize, DT_SMEMB);
    cudaFuncSetAttribute(scan_kernel4,
                         cudaFuncAttributeMaxDynamicSharedMemorySize, (int)sizeof(ScanSmem));

    // convert inputs to fp16 (+ dt_w hi/lo split)
    {
        int n4 = (MROWS * DMODEL) / 4;
        cvt_fp16_kernel<<<(n4 + 255) / 256, 256>>>(x, xh, n4);
        n4 = (DPROJ * DMODEL) / 4;
        cvt_fp16_kernel<<<(n4 + 255) / 256, 256>>>(in_proj, w1h, n4);
        n4 = (DMODEL * DINNER) / 4;
        cvt_fp16_kernel<<<(n4 + 255) / 256, 256>>>(out_w, w2h, n4);
        n4 = (DINNER * DTRANK) / 4;
        split_f16pair_kernel<<<(n4 + 255) / 256, 256>>>(dt_w, DTRANK, DTRANK, dtwh, dtwl, n4);
    }

    // 1) proj = x @ in_proj_w^T   [4096 x 4288]  (HMMA fp16, BK=64)
    gemm_mma_fp16<<<dim3((DPROJ + 127) / 128, MROWS / 128), 256, SMEMB>>>(
        xh, w1h, pproj, MROWS, DPROJ, DMODEL);

    // 2a) split delta_raw (proj cols 4224..4287) into fp16 hi/lo
    {
        int n4 = (MROWS * DTRANK) / 4;
        split_f16pair_kernel<<<(n4 + 255) / 256, 256>>>(
            pproj + 2 * DINNER + 2 * DSTATE, DPROJ, DTRANK, drh, drl, n4);
    }

    // 2b) delta = softplus(delta_raw @ dt_proj_w^T + b)   (HMMA hi/lo split, fp32-accurate)
    gemm_dt_split<<<dim3(DINNER / 128, MROWS / 128), 256, DT_SMEMB>>>(
        drh, drl, dtwh, dtwl, pdelta, dt_b);

    // 3) selective scan v4b (conv+silu fused, packed DU2); writes yh fp16 + hT tail
    scan_kernel4<<<256, 256, sizeof(ScanSmem)>>>(pproj, pdelta, A_log, D_param,
                                                 conv_w, conv_b,
                                                 yh, out + (size_t)MROWS * DMODEL);

    // 4) out = y @ out_proj_w^T   [4096 x 1024]  (HMMA fp16, BK=64)
    gemm_mma_fp16<<<dim3(DMODEL / 128, MROWS / 128), 256, SMEMB>>>(
        yh, w2h, out, MROWS, DMODEL, DINNER);
}